// round 2
// baseline (speedup 1.0000x reference)
#include <cuda_runtime.h>

#define S_LEN 2048
#define D_MODEL 1024
#define NHEAD 16
#define BATCH 2
#define BHEADS (BATCH * NHEAD)   // 32
#define DK 64
#define MROWS (BATCH * S_LEN)    // 4096

// ---------------- scratch (allocation-free: __device__ globals) ----------------
__device__ float g_q[(size_t)BHEADS * S_LEN * DK];  // 16 MB each
__device__ float g_k[(size_t)BHEADS * S_LEN * DK];
__device__ float g_v[(size_t)BHEADS * S_LEN * DK];
__device__ float g_o[(size_t)BHEADS * S_LEN * DK];

// =========================================================================
// Generic 128x128x16 fp32 GEMM core.  C[M,N] = A[M,K] @ W[K,N] + bias
// A_GATHER: read A from head-major [B*H, S, 64] scratch (for output proj)
// C_SCATTER: write C into head-major [B*H, S, 64] scratch (for qkv proj)
// M=4096, N=K=1024 fixed; 256 threads, 8x8 micro-tile.
// =========================================================================
template<int A_GATHER, int C_SCATTER>
__device__ __forceinline__ void gemm_core(
    const float* __restrict__ A, const float* __restrict__ W,
    const float* __restrict__ bias, float* __restrict__ C)
{
    __shared__ float As[16][132];   // transposed: As[k][m]
    __shared__ float Bs[16][132];   // Bs[k][n]

    const int tid = threadIdx.x;
    const int m0 = blockIdx.y * 128;
    const int n0 = blockIdx.x * 128;
    const int tx = tid & 15;
    const int ty = tid >> 4;

    float acc[8][8];
#pragma unroll
    for (int i = 0; i < 8; i++)
#pragma unroll
        for (int j = 0; j < 8; j++) acc[i][j] = 0.f;

    for (int k0 = 0; k0 < D_MODEL; k0 += 16) {
        // ---- load A tile (128m x 16k), 512 float4 total, 2 per thread ----
#pragma unroll
        for (int i = 0; i < 2; i++) {
            int idx = tid + i * 256;
            int m  = idx >> 2;
            int kq = (idx & 3) << 2;
            int gm = m0 + m;
            float4 v;
            if (A_GATHER) {
                int b = gm >> 11, s = gm & 2047;
                int gk = k0 + kq;
                int h = gk >> 6, d = gk & 63;
                v = *(const float4*)&A[(((size_t)(b * NHEAD + h) * S_LEN) + s) * DK + d];
            } else {
                v = *(const float4*)&A[(size_t)gm * D_MODEL + k0 + kq];
            }
            As[kq + 0][m] = v.x;
            As[kq + 1][m] = v.y;
            As[kq + 2][m] = v.z;
            As[kq + 3][m] = v.w;
        }
        // ---- load B tile (16k x 128n) ----
#pragma unroll
        for (int i = 0; i < 2; i++) {
            int idx = tid + i * 256;
            int kk = idx >> 5;
            int nq = (idx & 31) << 2;
            *(float4*)&Bs[kk][nq] = *(const float4*)&W[(size_t)(k0 + kk) * D_MODEL + n0 + nq];
        }
        __syncthreads();

#pragma unroll
        for (int kk = 0; kk < 16; kk++) {
            float a[8], b[8];
            *(float4*)&a[0] = *(const float4*)&As[kk][ty * 8];
            *(float4*)&a[4] = *(const float4*)&As[kk][ty * 8 + 4];
            *(float4*)&b[0] = *(const float4*)&Bs[kk][tx * 8];
            *(float4*)&b[4] = *(const float4*)&Bs[kk][tx * 8 + 4];
#pragma unroll
            for (int i = 0; i < 8; i++)
#pragma unroll
                for (int j = 0; j < 8; j++)
                    acc[i][j] = fmaf(a[i], b[j], acc[i][j]);
        }
        __syncthreads();
    }

    // ---- epilogue ----
#pragma unroll
    for (int i = 0; i < 8; i++) {
        int gm = m0 + ty * 8 + i;
#pragma unroll
        for (int j4 = 0; j4 < 8; j4 += 4) {
            int gn = n0 + tx * 8 + j4;
            float4 o;
            o.x = acc[i][j4 + 0] + bias[gn + 0];
            o.y = acc[i][j4 + 1] + bias[gn + 1];
            o.z = acc[i][j4 + 2] + bias[gn + 2];
            o.w = acc[i][j4 + 3] + bias[gn + 3];
            if (C_SCATTER) {
                int b = gm >> 11, s = gm & 2047;
                int h = gn >> 6, d = gn & 63;
                *(float4*)&C[(((size_t)(b * NHEAD + h) * S_LEN) + s) * DK + d] = o;
            } else {
                *(float4*)&C[(size_t)gm * D_MODEL + gn] = o;
            }
        }
    }
}

__global__ void __launch_bounds__(256, 2) proj_kernel(
    const float* __restrict__ Xq, const float* __restrict__ Xk, const float* __restrict__ Xv,
    const float* __restrict__ Wq, const float* __restrict__ Wk, const float* __restrict__ Wv,
    const float* __restrict__ bq, const float* __restrict__ bk, const float* __restrict__ bv)
{
    int z = blockIdx.z;
    const float* A    = (z == 0) ? Xq : (z == 1) ? Xk : Xv;
    const float* W    = (z == 0) ? Wq : (z == 1) ? Wk : Wv;
    const float* bias = (z == 0) ? bq : (z == 1) ? bk : bv;
    float*       C    = (z == 0) ? g_q : (z == 1) ? g_k : g_v;
    gemm_core<0, 1>(A, W, bias, C);
}

__global__ void __launch_bounds__(256, 2) outproj_kernel(
    const float* __restrict__ Wo, const float* __restrict__ bo, float* __restrict__ C)
{
    gemm_core<1, 0>(g_o, Wo, bo, C);
}

// =========================================================================
// Flash attention with relative positional bias.
// One block = 64 query rows of one (b,h).  256 threads.
// Per KV tile (64 cols):
//   score GEMM: SC[64, 191] = Q[64,64] @ [K_tile(64) || PE_band(127)]^T
//   combine:    s[r,c] = (SC[r,c] + SC[r, 127 + c - r]) * (1/8), causal -1e9
//   online softmax (4 threads / row), then PV GEMM with per-row rescale.
// SMEM layout (floats):
//   Qs  [64][68]  d-major (Qs[d][r])           @ 0      (4352)
//   KP  [64][200] d-major (KP[d][j], j<191)    @ 4352   (12800)
//   SC  [64][196] row-major, ALIASES KP        @ 4352   (12544)
//   Ps  [64][68]  c-major (Ps[c][r])           @ 17152  (4352)
//   Vs  [64][68]  row-major (Vs[c][d])         @ 21504  (4352)
//   alpha[64] @ 25856, lsum[64] @ 25920        -> total 25984 floats = 103936 B
// =========================================================================
#define QS_OFF 0
#define KP_OFF 4352
#define SC_OFF 4352
#define PS_OFF 17152
#define VS_OFF 21504
#define AL_OFF 25856
#define LS_OFF 25920
#define FLASH_SMEM_BYTES (25984 * 4)

__global__ void __launch_bounds__(256, 2) flash_kernel(const float* __restrict__ pe)
{
    extern __shared__ float sm[];
    const int tid = threadIdx.x;
    const int bh  = blockIdx.y;
    const int rt  = (int)gridDim.x - 1 - (int)blockIdx.x;  // heavy tiles first
    const int r0  = rt * 64;

    const float* Qg = g_q + (size_t)bh * S_LEN * DK;
    const float* Kg = g_k + (size_t)bh * S_LEN * DK;
    const float* Vg = g_v + (size_t)bh * S_LEN * DK;
    float*       Og = g_o + (size_t)bh * S_LEN * DK;

    const int tg = tid >> 4;   // 0..15 : GEMM row-group (rows tg*4..tg*4+3)
    const int tl = tid & 15;   // 0..15 : GEMM col-group
    const int srow = tid >> 2; // 0..63 : softmax row
    const int sc4  = tid & 3;  // 0..3  : softmax col quarter

    // ---- load Q tile, transposed to d-major ----
#pragma unroll
    for (int i = 0; i < 4; i++) {
        int idx = tid + i * 256;
        int r  = idx & 63;
        int dq = (idx >> 6) << 2;
        float4 v = *(const float4*)&Qg[(size_t)(r0 + r) * DK + dq];
        sm[QS_OFF + (dq + 0) * 68 + r] = v.x;
        sm[QS_OFF + (dq + 1) * 68 + r] = v.y;
        sm[QS_OFF + (dq + 2) * 68 + r] = v.z;
        sm[QS_OFF + (dq + 3) * 68 + r] = v.w;
    }

    float Oacc[4][4];
#pragma unroll
    for (int i = 0; i < 4; i++)
#pragma unroll
        for (int j = 0; j < 4; j++) Oacc[i][j] = 0.f;
    float m_old = -1.0e30f;
    float l_old = 0.f;

    const int ntiles = rt + 1;
    for (int t = 0; t < ntiles; t++) {
        const int c0 = t * 64;
        const int base_lo = S_LEN - 64 - r0 + c0;   // PE band: l = base_lo + jr
        __syncthreads();   // previous PV done before overwriting KP/Vs

        // ---- K tile -> KP[d][0..63] (transposed) ----
#pragma unroll
        for (int i = 0; i < 4; i++) {
            int idx = tid + i * 256;
            int c  = idx & 63;
            int dq = (idx >> 6) << 2;
            float4 v = *(const float4*)&Kg[(size_t)(c0 + c) * DK + dq];
            sm[KP_OFF + (dq + 0) * 200 + c] = v.x;
            sm[KP_OFF + (dq + 1) * 200 + c] = v.y;
            sm[KP_OFF + (dq + 2) * 200 + c] = v.z;
            sm[KP_OFF + (dq + 3) * 200 + c] = v.w;
        }
        // ---- PE band (127 rows) -> KP[d][64..190], plus zero col 191 ----
#pragma unroll
        for (int i = 0; i < 8; i++) {
            int idx = tid + i * 256;        // 0..2047
            int jr = idx & 127;
            int dq = (idx >> 7) << 2;
            if (jr < 127) {
                int l = base_lo + jr;
                float4 v;
                if (l >= 0 && l < S_LEN) v = *(const float4*)&pe[(size_t)l * DK + dq];
                else                     v = make_float4(0.f, 0.f, 0.f, 0.f);
                sm[KP_OFF + (dq + 0) * 200 + 64 + jr] = v.x;
                sm[KP_OFF + (dq + 1) * 200 + 64 + jr] = v.y;
                sm[KP_OFF + (dq + 2) * 200 + 64 + jr] = v.z;
                sm[KP_OFF + (dq + 3) * 200 + 64 + jr] = v.w;
            } else {
                sm[KP_OFF + (dq + 0) * 200 + 191] = 0.f;
                sm[KP_OFF + (dq + 1) * 200 + 191] = 0.f;
                sm[KP_OFF + (dq + 2) * 200 + 191] = 0.f;
                sm[KP_OFF + (dq + 3) * 200 + 191] = 0.f;
            }
        }
        // ---- V tile -> Vs[c][d] (natural layout) ----
#pragma unroll
        for (int i = 0; i < 4; i++) {
            int idx = tid + i * 256;
            int c  = idx >> 4;
            int dq = (idx & 15) << 2;
            *(float4*)&sm[VS_OFF + c * 68 + dq] =
                *(const float4*)&Vg[(size_t)(c0 + c) * DK + dq];
        }
        __syncthreads();

        // ---- score GEMM: acc[4][12] over rows tg*4.., cols tl*12.. ----
        float acc[4][12];
#pragma unroll
        for (int i = 0; i < 4; i++)
#pragma unroll
            for (int j = 0; j < 12; j++) acc[i][j] = 0.f;

#pragma unroll 4
        for (int d = 0; d < 64; d++) {
            float a[4];
            *(float4*)a = *(const float4*)&sm[QS_OFF + d * 68 + tg * 4];
            float bb[12];
            *(float4*)&bb[0] = *(const float4*)&sm[KP_OFF + d * 200 + tl * 12];
            *(float4*)&bb[4] = *(const float4*)&sm[KP_OFF + d * 200 + tl * 12 + 4];
            *(float4*)&bb[8] = *(const float4*)&sm[KP_OFF + d * 200 + tl * 12 + 8];
#pragma unroll
            for (int i = 0; i < 4; i++)
#pragma unroll
                for (int j = 0; j < 12; j++)
                    acc[i][j] = fmaf(a[i], bb[j], acc[i][j]);
        }
        __syncthreads();   // everyone done reading KP before SC overwrite

        // ---- dump acc -> SC (aliases KP) ----
#pragma unroll
        for (int i = 0; i < 4; i++)
#pragma unroll
            for (int j4 = 0; j4 < 12; j4 += 4)
                *(float4*)&sm[SC_OFF + (tg * 4 + i) * 196 + tl * 12 + j4] =
                    *(float4*)&acc[i][j4];
        __syncthreads();

        // ---- softmax (4 threads per row, 16 cols each) ----
        {
            const int r  = srow;
            const int gr = r0 + r;
            const int cb = sc4 * 16;
            float s[16];
            float mt = -1.0e30f;
#pragma unroll
            for (int i = 0; i < 16; i++) {
                int c = cb + i;
                float val = (sm[SC_OFF + r * 196 + c] +
                             sm[SC_OFF + r * 196 + 127 + c - r]) * 0.125f;
                if (c0 + c > gr) val = -1.0e9f;   // exact ref mask value
                s[i] = val;
                mt = fmaxf(mt, val);
            }
            mt = fmaxf(mt, __shfl_xor_sync(0xffffffffu, mt, 1));
            mt = fmaxf(mt, __shfl_xor_sync(0xffffffffu, mt, 2));
            float m_new = fmaxf(m_old, mt);
            float al = __expf(m_old - m_new);
            float psum = 0.f;
#pragma unroll
            for (int i = 0; i < 16; i++) {
                float p = __expf(s[i] - m_new);
                psum += p;
                sm[PS_OFF + (cb + i) * 68 + r] = p;
            }
            psum += __shfl_xor_sync(0xffffffffu, psum, 1);
            psum += __shfl_xor_sync(0xffffffffu, psum, 2);
            float l_new = fmaf(al, l_old, psum);
            m_old = m_new;
            l_old = l_new;
            if (sc4 == 0) {
                sm[AL_OFF + r] = al;
                sm[LS_OFF + r] = l_new;
            }
        }
        __syncthreads();

        // ---- PV GEMM with per-row rescale; rows tg*4.., dv cols tl*4.. ----
#pragma unroll
        for (int i = 0; i < 4; i++) {
            float al = sm[AL_OFF + tg * 4 + i];
#pragma unroll
            for (int j = 0; j < 4; j++) Oacc[i][j] *= al;
        }
#pragma unroll 8
        for (int c = 0; c < 64; c++) {
            float a[4], b4[4];
            *(float4*)a  = *(const float4*)&sm[PS_OFF + c * 68 + tg * 4];
            *(float4*)b4 = *(const float4*)&sm[VS_OFF + c * 68 + tl * 4];
#pragma unroll
            for (int i = 0; i < 4; i++)
#pragma unroll
                for (int j = 0; j < 4; j++)
                    Oacc[i][j] = fmaf(a[i], b4[j], Oacc[i][j]);
        }
    }

    // ---- normalize + store (lsum was written before last pre-PV sync) ----
#pragma unroll
    for (int i = 0; i < 4; i++) {
        float inv = 1.0f / sm[LS_OFF + tg * 4 + i];
        float4 o;
        o.x = Oacc[i][0] * inv;
        o.y = Oacc[i][1] * inv;
        o.z = Oacc[i][2] * inv;
        o.w = Oacc[i][3] * inv;
        *(float4*)&Og[(size_t)(r0 + tg * 4 + i) * DK + tl * 4] = o;
    }
}

// =========================================================================
// kernel_launch
// Inputs (metadata order): query, key, value, key_pe, Wq, bq, Wk, bk,
//                          Wv, bv, Wo, bo, attn_span
// attn_span == S always -> the "else" (full-skew) branch is hardcoded.
// =========================================================================
extern "C" void kernel_launch(void* const* d_in, const int* in_sizes, int n_in,
                              void* d_out, int out_size)
{
    const float* query  = (const float*)d_in[0];
    const float* key    = (const float*)d_in[1];
    const float* value  = (const float*)d_in[2];
    const float* key_pe = (const float*)d_in[3];
    const float* Wq = (const float*)d_in[4];
    const float* bq = (const float*)d_in[5];
    const float* Wk = (const float*)d_in[6];
    const float* bk = (const float*)d_in[7];
    const float* Wv = (const float*)d_in[8];
    const float* bv = (const float*)d_in[9];
    const float* Wo = (const float*)d_in[10];
    const float* bo = (const float*)d_in[11];
    float* out = (float*)d_out;

    cudaFuncSetAttribute(flash_kernel,
                         cudaFuncAttributeMaxDynamicSharedMemorySize,
                         FLASH_SMEM_BYTES);

    // 1) Q/K/V projections into head-major scratch
    dim3 gproj(D_MODEL / 128, MROWS / 128, 3);   // (8, 32, 3)
    proj_kernel<<<gproj, 256>>>(query, key, value, Wq, Wk, Wv, bq, bk, bv);

    // 2) causal attention + relative positional bias
    flash_kernel<<<dim3(S_LEN / 64, BHEADS), 256, FLASH_SMEM_BYTES>>>(key_pe);

    // 3) output projection
    outproj_kernel<<<dim3(D_MODEL / 128, MROWS / 128), 256>>>(Wo, bo, out);
}

// round 7
// speedup vs baseline: 1.3501x; 1.3501x over previous
#include <cuda_runtime.h>
#include <cstdint>

#define S_LEN 2048
#define D_MODEL 1024
#define NHEAD 16
#define BATCH 2
#define BHEADS (BATCH * NHEAD)   // 32
#define DK 64
#define MROWS (BATCH * S_LEN)    // 4096

// ---------------- scratch (allocation-free: __device__ globals) ----------------
__device__ float g_q[(size_t)BHEADS * S_LEN * DK];
__device__ float g_k[(size_t)BHEADS * S_LEN * DK];
__device__ float g_v[(size_t)BHEADS * S_LEN * DK];
__device__ float g_o[(size_t)BHEADS * S_LEN * DK];

// ======================= helpers =======================
__device__ __forceinline__ uint32_t f2tf32(float f) {
    uint32_t r;
    asm("cvt.rna.tf32.f32 %0, %1;" : "=r"(r) : "f"(f));
    return r;
}

// m16n8k8 tf32 mma: A row-major (4 regs), B col-major (2 regs), C f32 (4 regs)
__device__ __forceinline__ void mma8(float c[4], const uint32_t a[4], const uint32_t b[2]) {
    asm volatile(
        "mma.sync.aligned.m16n8k8.row.col.f32.tf32.tf32.f32 "
        "{%0,%1,%2,%3}, {%4,%5,%6,%7}, {%8,%9}, {%0,%1,%2,%3};"
        : "+f"(c[0]), "+f"(c[1]), "+f"(c[2]), "+f"(c[3])
        : "r"(a[0]), "r"(a[1]), "r"(a[2]), "r"(a[3]), "r"(b[0]), "r"(b[1]));
}

// =========================================================================
// Dense GEMM via mma.sync tf32:  C[4096,1024] = A[4096,1024] @ W[1024,1024] + bias
// Block 128x128, 8 warps (2m x 4n), warp tile 64x32, BK=16.
// SMEM: As[m][k] stride 20 (frag loads conflict-free: (20m+k)%32 covers all banks),
//       Bs[k][n] stride 136 (frag loads conflict-free: (8k+n)%32).
// Register-prefetch pipeline, 2 syncs per k-tile.
// =========================================================================
template<int A_GATHER, int C_SCATTER>
__device__ __forceinline__ void mma_gemm(
    const float* __restrict__ A, const float* __restrict__ W,
    const float* __restrict__ bias, float* __restrict__ C)
{
    __shared__ uint32_t As[128 * 20];
    __shared__ uint32_t Bs[16 * 136];

    const int tid  = threadIdx.x;
    const int lane = tid & 31;
    const int wid  = tid >> 5;
    const int mw = (wid >> 2) * 64;   // 0 / 64
    const int nw = (wid & 3) * 32;    // 0..96
    const int m0 = blockIdx.y * 128;
    const int n0 = blockIdx.x * 128;

    float4 ra[2], rb[2];

    auto fetch = [&](int k0) {
#pragma unroll
        for (int i = 0; i < 2; i++) {
            int idx = tid + i * 256;
            int m = idx >> 2, kq = (idx & 3) << 2;
            if (A_GATHER) {
                int gm = m0 + m, b = gm >> 11, s2 = gm & 2047;
                int gk = k0 + kq, h = gk >> 6, d = gk & 63;
                ra[i] = *(const float4*)&A[(((size_t)(b * NHEAD + h)) * S_LEN + s2) * DK + d];
            } else {
                ra[i] = *(const float4*)&A[(size_t)(m0 + m) * D_MODEL + k0 + kq];
            }
            int kk = idx >> 5, nq = (idx & 31) << 2;
            rb[i] = *(const float4*)&W[(size_t)(k0 + kk) * D_MODEL + n0 + nq];
        }
    };
    auto deposit = [&]() {
#pragma unroll
        for (int i = 0; i < 2; i++) {
            int idx = tid + i * 256;
            int m = idx >> 2, kq = (idx & 3) << 2;
            As[m * 20 + kq + 0] = f2tf32(ra[i].x);
            As[m * 20 + kq + 1] = f2tf32(ra[i].y);
            As[m * 20 + kq + 2] = f2tf32(ra[i].z);
            As[m * 20 + kq + 3] = f2tf32(ra[i].w);
            int kk = idx >> 5, nq = (idx & 31) << 2;
            Bs[kk * 136 + nq + 0] = f2tf32(rb[i].x);
            Bs[kk * 136 + nq + 1] = f2tf32(rb[i].y);
            Bs[kk * 136 + nq + 2] = f2tf32(rb[i].z);
            Bs[kk * 136 + nq + 3] = f2tf32(rb[i].w);
        }
    };

    float acc[4][4][4];
#pragma unroll
    for (int mi = 0; mi < 4; mi++)
#pragma unroll
        for (int ni = 0; ni < 4; ni++)
#pragma unroll
            for (int q = 0; q < 4; q++) acc[mi][ni][q] = 0.f;

    fetch(0);
    deposit();
    __syncthreads();

    for (int kt = 0; kt < 64; kt++) {
        if (kt < 63) fetch((kt + 1) * 16);
#pragma unroll
        for (int k8 = 0; k8 < 2; k8++) {
            const int kb = k8 * 8 + (lane & 3);
            uint32_t a[4][4], b[4][2];
#pragma unroll
            for (int mi = 0; mi < 4; mi++) {
                int r = mw + mi * 16 + (lane >> 2);
                a[mi][0] = As[r * 20 + kb];
                a[mi][1] = As[(r + 8) * 20 + kb];
                a[mi][2] = As[r * 20 + kb + 4];
                a[mi][3] = As[(r + 8) * 20 + kb + 4];
            }
#pragma unroll
            for (int ni = 0; ni < 4; ni++) {
                int n = nw + ni * 8 + (lane >> 2);
                b[ni][0] = Bs[kb * 136 + n];
                b[ni][1] = Bs[(kb + 4) * 136 + n];
            }
#pragma unroll
            for (int mi = 0; mi < 4; mi++)
#pragma unroll
                for (int ni = 0; ni < 4; ni++)
                    mma8(acc[mi][ni], a[mi], b[ni]);
        }
        if (kt < 63) {
            __syncthreads();   // all reads of current tile done
            deposit();
            __syncthreads();   // new tile visible
        }
    }

    // epilogue: fragment -> global (float2 pairs), + bias
#pragma unroll
    for (int mi = 0; mi < 4; mi++) {
        int r = m0 + mw + mi * 16 + (lane >> 2);
#pragma unroll
        for (int ni = 0; ni < 4; ni++) {
            int cn = n0 + nw + ni * 8 + (lane & 3) * 2;
            float bx = bias[cn], by = bias[cn + 1];
            float2 lo = { acc[mi][ni][0] + bx, acc[mi][ni][1] + by };
            float2 hi = { acc[mi][ni][2] + bx, acc[mi][ni][3] + by };
            if (C_SCATTER) {
                int h = cn >> 6, d = cn & 63;
                int b0 = r >> 11, s2 = r & 2047;
                *(float2*)&C[(((size_t)(b0 * NHEAD + h)) * S_LEN + s2) * DK + d] = lo;
                int r2 = r + 8, b1 = r2 >> 11, s3 = r2 & 2047;
                *(float2*)&C[(((size_t)(b1 * NHEAD + h)) * S_LEN + s3) * DK + d] = hi;
            } else {
                *(float2*)&C[(size_t)r * D_MODEL + cn] = lo;
                *(float2*)&C[(size_t)(r + 8) * D_MODEL + cn] = hi;
            }
        }
    }
}

__global__ void __launch_bounds__(256) proj_kernel(
    const float* __restrict__ Xq, const float* __restrict__ Xk, const float* __restrict__ Xv,
    const float* __restrict__ Wq, const float* __restrict__ Wk, const float* __restrict__ Wv,
    const float* __restrict__ bq, const float* __restrict__ bk, const float* __restrict__ bv)
{
    int z = blockIdx.z;
    const float* A    = (z == 0) ? Xq : (z == 1) ? Xk : Xv;
    const float* W    = (z == 0) ? Wq : (z == 1) ? Wk : Wv;
    const float* bias = (z == 0) ? bq : (z == 1) ? bk : bv;
    float*       Cp   = (z == 0) ? g_q : (z == 1) ? g_k : g_v;
    mma_gemm<0, 1>(A, W, bias, Cp);
}

__global__ void __launch_bounds__(256) outproj_kernel(
    const float* __restrict__ Wo, const float* __restrict__ bo, float* __restrict__ C)
{
    mma_gemm<1, 0>(g_o, Wo, bo, C);
}

// =========================================================================
// Flash attention with relative positional bias — VERBATIM from Round 1
// (passed, rel_err 6e-7).  One block = 64 query rows of one (b,h).
// SMEM layout (floats):
//   Qs  [64][68]  d-major (Qs[d][r])           @ 0      (4352)
//   KP  [64][200] d-major (KP[d][j], j<191)    @ 4352   (12800)
//   SC  [64][196] row-major, ALIASES KP        @ 4352   (12544)
//   Ps  [64][68]  c-major (Ps[c][r])           @ 17152  (4352)
//   Vs  [64][68]  row-major (Vs[c][d])         @ 21504  (4352)
//   alpha[64] @ 25856, lsum[64] @ 25920        -> total 25984 floats = 103936 B
// =========================================================================
#define QS_OFF 0
#define KP_OFF 4352
#define SC_OFF 4352
#define PS_OFF 17152
#define VS_OFF 21504
#define AL_OFF 25856
#define LS_OFF 25920
#define FLASH_SMEM_BYTES (25984 * 4)

__global__ void __launch_bounds__(256, 2) flash_kernel(const float* __restrict__ pe)
{
    extern __shared__ float sm[];
    const int tid = threadIdx.x;
    const int bh  = blockIdx.y;
    const int rt  = (int)gridDim.x - 1 - (int)blockIdx.x;  // heavy tiles first
    const int r0  = rt * 64;

    const float* Qg = g_q + (size_t)bh * S_LEN * DK;
    const float* Kg = g_k + (size_t)bh * S_LEN * DK;
    const float* Vg = g_v + (size_t)bh * S_LEN * DK;
    float*       Og = g_o + (size_t)bh * S_LEN * DK;

    const int tg = tid >> 4;   // 0..15 : GEMM row-group (rows tg*4..tg*4+3)
    const int tl = tid & 15;   // 0..15 : GEMM col-group
    const int srow = tid >> 2; // 0..63 : softmax row
    const int sc4  = tid & 3;  // 0..3  : softmax col quarter

    // ---- load Q tile, transposed to d-major ----
#pragma unroll
    for (int i = 0; i < 4; i++) {
        int idx = tid + i * 256;
        int r  = idx & 63;
        int dq = (idx >> 6) << 2;
        float4 v = *(const float4*)&Qg[(size_t)(r0 + r) * DK + dq];
        sm[QS_OFF + (dq + 0) * 68 + r] = v.x;
        sm[QS_OFF + (dq + 1) * 68 + r] = v.y;
        sm[QS_OFF + (dq + 2) * 68 + r] = v.z;
        sm[QS_OFF + (dq + 3) * 68 + r] = v.w;
    }

    float Oacc[4][4];
#pragma unroll
    for (int i = 0; i < 4; i++)
#pragma unroll
        for (int j = 0; j < 4; j++) Oacc[i][j] = 0.f;
    float m_old = -1.0e30f;
    float l_old = 0.f;

    const int ntiles = rt + 1;
    for (int t = 0; t < ntiles; t++) {
        const int c0 = t * 64;
        const int base_lo = S_LEN - 64 - r0 + c0;   // PE band: l = base_lo + jr
        __syncthreads();   // previous PV done before overwriting KP/Vs

        // ---- K tile -> KP[d][0..63] (transposed) ----
#pragma unroll
        for (int i = 0; i < 4; i++) {
            int idx = tid + i * 256;
            int c  = idx & 63;
            int dq = (idx >> 6) << 2;
            float4 v = *(const float4*)&Kg[(size_t)(c0 + c) * DK + dq];
            sm[KP_OFF + (dq + 0) * 200 + c] = v.x;
            sm[KP_OFF + (dq + 1) * 200 + c] = v.y;
            sm[KP_OFF + (dq + 2) * 200 + c] = v.z;
            sm[KP_OFF + (dq + 3) * 200 + c] = v.w;
        }
        // ---- PE band (127 rows) -> KP[d][64..190], plus zero col 191 ----
#pragma unroll
        for (int i = 0; i < 8; i++) {
            int idx = tid + i * 256;        // 0..2047
            int jr = idx & 127;
            int dq = (idx >> 7) << 2;
            if (jr < 127) {
                int l = base_lo + jr;
                float4 v;
                if (l >= 0 && l < S_LEN) v = *(const float4*)&pe[(size_t)l * DK + dq];
                else                     v = make_float4(0.f, 0.f, 0.f, 0.f);
                sm[KP_OFF + (dq + 0) * 200 + 64 + jr] = v.x;
                sm[KP_OFF + (dq + 1) * 200 + 64 + jr] = v.y;
                sm[KP_OFF + (dq + 2) * 200 + 64 + jr] = v.z;
                sm[KP_OFF + (dq + 3) * 200 + 64 + jr] = v.w;
            } else {
                sm[KP_OFF + (dq + 0) * 200 + 191] = 0.f;
                sm[KP_OFF + (dq + 1) * 200 + 191] = 0.f;
                sm[KP_OFF + (dq + 2) * 200 + 191] = 0.f;
                sm[KP_OFF + (dq + 3) * 200 + 191] = 0.f;
            }
        }
        // ---- V tile -> Vs[c][d] (natural layout) ----
#pragma unroll
        for (int i = 0; i < 4; i++) {
            int idx = tid + i * 256;
            int c  = idx >> 4;
            int dq = (idx & 15) << 2;
            *(float4*)&sm[VS_OFF + c * 68 + dq] =
                *(const float4*)&Vg[(size_t)(c0 + c) * DK + dq];
        }
        __syncthreads();

        // ---- score GEMM: acc[4][12] over rows tg*4.., cols tl*12.. ----
        float acc[4][12];
#pragma unroll
        for (int i = 0; i < 4; i++)
#pragma unroll
            for (int j = 0; j < 12; j++) acc[i][j] = 0.f;

#pragma unroll 4
        for (int d = 0; d < 64; d++) {
            float a[4];
            *(float4*)a = *(const float4*)&sm[QS_OFF + d * 68 + tg * 4];
            float bb[12];
            *(float4*)&bb[0] = *(const float4*)&sm[KP_OFF + d * 200 + tl * 12];
            *(float4*)&bb[4] = *(const float4*)&sm[KP_OFF + d * 200 + tl * 12 + 4];
            *(float4*)&bb[8] = *(const float4*)&sm[KP_OFF + d * 200 + tl * 12 + 8];
#pragma unroll
            for (int i = 0; i < 4; i++)
#pragma unroll
                for (int j = 0; j < 12; j++)
                    acc[i][j] = fmaf(a[i], bb[j], acc[i][j]);
        }
        __syncthreads();   // everyone done reading KP before SC overwrite

        // ---- dump acc -> SC (aliases KP) ----
#pragma unroll
        for (int i = 0; i < 4; i++)
#pragma unroll
            for (int j4 = 0; j4 < 12; j4 += 4)
                *(float4*)&sm[SC_OFF + (tg * 4 + i) * 196 + tl * 12 + j4] =
                    *(float4*)&acc[i][j4];
        __syncthreads();

        // ---- softmax (4 threads per row, 16 cols each) ----
        {
            const int r  = srow;
            const int gr = r0 + r;
            const int cb = sc4 * 16;
            float s[16];
            float mt = -1.0e30f;
#pragma unroll
            for (int i = 0; i < 16; i++) {
                int c = cb + i;
                float val = (sm[SC_OFF + r * 196 + c] +
                             sm[SC_OFF + r * 196 + 127 + c - r]) * 0.125f;
                if (c0 + c > gr) val = -1.0e9f;   // exact ref mask value
                s[i] = val;
                mt = fmaxf(mt, val);
            }
            mt = fmaxf(mt, __shfl_xor_sync(0xffffffffu, mt, 1));
            mt = fmaxf(mt, __shfl_xor_sync(0xffffffffu, mt, 2));
            float m_new = fmaxf(m_old, mt);
            float al = __expf(m_old - m_new);
            float psum = 0.f;
#pragma unroll
            for (int i = 0; i < 16; i++) {
                float p = __expf(s[i] - m_new);
                psum += p;
                sm[PS_OFF + (cb + i) * 68 + r] = p;
            }
            psum += __shfl_xor_sync(0xffffffffu, psum, 1);
            psum += __shfl_xor_sync(0xffffffffu, psum, 2);
            float l_new = fmaf(al, l_old, psum);
            m_old = m_new;
            l_old = l_new;
            if (sc4 == 0) {
                sm[AL_OFF + r] = al;
                sm[LS_OFF + r] = l_new;
            }
        }
        __syncthreads();

        // ---- PV GEMM with per-row rescale; rows tg*4.., dv cols tl*4.. ----
#pragma unroll
        for (int i = 0; i < 4; i++) {
            float al = sm[AL_OFF + tg * 4 + i];
#pragma unroll
            for (int j = 0; j < 4; j++) Oacc[i][j] *= al;
        }
#pragma unroll 8
        for (int c = 0; c < 64; c++) {
            float a[4], b4[4];
            *(float4*)a  = *(const float4*)&sm[PS_OFF + c * 68 + tg * 4];
            *(float4*)b4 = *(const float4*)&sm[VS_OFF + c * 68 + tl * 4];
#pragma unroll
            for (int i = 0; i < 4; i++)
#pragma unroll
                for (int j = 0; j < 4; j++)
                    Oacc[i][j] = fmaf(a[i], b4[j], Oacc[i][j]);
        }
    }

    // ---- normalize + store ----
#pragma unroll
    for (int i = 0; i < 4; i++) {
        float inv = 1.0f / sm[LS_OFF + tg * 4 + i];
        float4 o;
        o.x = Oacc[i][0] * inv;
        o.y = Oacc[i][1] * inv;
        o.z = Oacc[i][2] * inv;
        o.w = Oacc[i][3] * inv;
        *(float4*)&Og[(size_t)(r0 + tg * 4 + i) * DK + tl * 4] = o;
    }
}

// =========================================================================
extern "C" void kernel_launch(void* const* d_in, const int* in_sizes, int n_in,
                              void* d_out, int out_size)
{
    const float* query  = (const float*)d_in[0];
    const float* key    = (const float*)d_in[1];
    const float* value  = (const float*)d_in[2];
    const float* key_pe = (const float*)d_in[3];
    const float* Wq = (const float*)d_in[4];
    const float* bq = (const float*)d_in[5];
    const float* Wk = (const float*)d_in[6];
    const float* bk = (const float*)d_in[7];
    const float* Wv = (const float*)d_in[8];
    const float* bv = (const float*)d_in[9];
    const float* Wo = (const float*)d_in[10];
    const float* bo = (const float*)d_in[11];
    float* out = (float*)d_out;

    cudaFuncSetAttribute(flash_kernel,
                         cudaFuncAttributeMaxDynamicSharedMemorySize,
                         FLASH_SMEM_BYTES);

    // 1) Q/K/V projections (mma.sync tf32)
    proj_kernel<<<dim3(8, 32, 3), 256>>>(query, key, value, Wq, Wk, Wv, bq, bk, bv);

    // 2) causal attention + relative positional bias (fp32 SIMT, proven)
    flash_kernel<<<dim3(S_LEN / 64, BHEADS), 256, FLASH_SMEM_BYTES>>>(key_pe);

    // 3) output projection (mma.sync tf32)
    outproj_kernel<<<dim3(8, 32), 256>>>(Wo, bo, out);
}

// round 8
// speedup vs baseline: 2.7683x; 2.0504x over previous
#include <cuda_runtime.h>
#include <cstdint>

#define S_LEN 2048
#define D_MODEL 1024
#define NHEAD 16
#define BATCH 2
#define BHEADS (BATCH * NHEAD)   // 32
#define DK 64
#define MROWS (BATCH * S_LEN)    // 4096

// ---------------- scratch (allocation-free: __device__ globals) ----------------
__device__ float g_q[(size_t)BHEADS * S_LEN * DK];
__device__ float g_k[(size_t)BHEADS * S_LEN * DK];
__device__ float g_v[(size_t)BHEADS * S_LEN * DK];
__device__ float g_o[(size_t)BHEADS * S_LEN * DK];

// ======================= helpers =======================
__device__ __forceinline__ uint32_t f2tf32(float f) {
    uint32_t r;
    asm("cvt.rna.tf32.f32 %0, %1;" : "=r"(r) : "f"(f));
    return r;
}

// m16n8k8 tf32 mma: A row-major (4 regs), B col-major (2 regs), C f32 (4 regs)
__device__ __forceinline__ void mma8(float c[4], const uint32_t a[4], const uint32_t b[2]) {
    asm volatile(
        "mma.sync.aligned.m16n8k8.row.col.f32.tf32.tf32.f32 "
        "{%0,%1,%2,%3}, {%4,%5,%6,%7}, {%8,%9}, {%0,%1,%2,%3};"
        : "+f"(c[0]), "+f"(c[1]), "+f"(c[2]), "+f"(c[3])
        : "r"(a[0]), "r"(a[1]), "r"(a[2]), "r"(a[3]), "r"(b[0]), "r"(b[1]));
}

// =========================================================================
// Dense GEMM via mma.sync tf32 (PROVEN in R6):
// C[4096,1024] = A[4096,1024] @ W[1024,1024] + bias
// =========================================================================
template<int A_GATHER, int C_SCATTER>
__device__ __forceinline__ void mma_gemm(
    const float* __restrict__ A, const float* __restrict__ W,
    const float* __restrict__ bias, float* __restrict__ C)
{
    __shared__ uint32_t As[128 * 20];
    __shared__ uint32_t Bs[16 * 136];

    const int tid  = threadIdx.x;
    const int lane = tid & 31;
    const int wid  = tid >> 5;
    const int mw = (wid >> 2) * 64;
    const int nw = (wid & 3) * 32;
    const int m0 = blockIdx.y * 128;
    const int n0 = blockIdx.x * 128;

    float4 ra[2], rb[2];

    auto fetch = [&](int k0) {
#pragma unroll
        for (int i = 0; i < 2; i++) {
            int idx = tid + i * 256;
            int m = idx >> 2, kq = (idx & 3) << 2;
            if (A_GATHER) {
                int gm = m0 + m, b = gm >> 11, s2 = gm & 2047;
                int gk = k0 + kq, h = gk >> 6, d = gk & 63;
                ra[i] = *(const float4*)&A[(((size_t)(b * NHEAD + h)) * S_LEN + s2) * DK + d];
            } else {
                ra[i] = *(const float4*)&A[(size_t)(m0 + m) * D_MODEL + k0 + kq];
            }
            int kk = idx >> 5, nq = (idx & 31) << 2;
            rb[i] = *(const float4*)&W[(size_t)(k0 + kk) * D_MODEL + n0 + nq];
        }
    };
    auto deposit = [&]() {
#pragma unroll
        for (int i = 0; i < 2; i++) {
            int idx = tid + i * 256;
            int m = idx >> 2, kq = (idx & 3) << 2;
            As[m * 20 + kq + 0] = f2tf32(ra[i].x);
            As[m * 20 + kq + 1] = f2tf32(ra[i].y);
            As[m * 20 + kq + 2] = f2tf32(ra[i].z);
            As[m * 20 + kq + 3] = f2tf32(ra[i].w);
            int kk = idx >> 5, nq = (idx & 31) << 2;
            Bs[kk * 136 + nq + 0] = f2tf32(rb[i].x);
            Bs[kk * 136 + nq + 1] = f2tf32(rb[i].y);
            Bs[kk * 136 + nq + 2] = f2tf32(rb[i].z);
            Bs[kk * 136 + nq + 3] = f2tf32(rb[i].w);
        }
    };

    float acc[4][4][4];
#pragma unroll
    for (int mi = 0; mi < 4; mi++)
#pragma unroll
        for (int ni = 0; ni < 4; ni++)
#pragma unroll
            for (int q = 0; q < 4; q++) acc[mi][ni][q] = 0.f;

    fetch(0);
    deposit();
    __syncthreads();

    for (int kt = 0; kt < 64; kt++) {
        if (kt < 63) fetch((kt + 1) * 16);
#pragma unroll
        for (int k8 = 0; k8 < 2; k8++) {
            const int kb = k8 * 8 + (lane & 3);
            uint32_t a[4][4], b[4][2];
#pragma unroll
            for (int mi = 0; mi < 4; mi++) {
                int r = mw + mi * 16 + (lane >> 2);
                a[mi][0] = As[r * 20 + kb];
                a[mi][1] = As[(r + 8) * 20 + kb];
                a[mi][2] = As[r * 20 + kb + 4];
                a[mi][3] = As[(r + 8) * 20 + kb + 4];
            }
#pragma unroll
            for (int ni = 0; ni < 4; ni++) {
                int n = nw + ni * 8 + (lane >> 2);
                b[ni][0] = Bs[kb * 136 + n];
                b[ni][1] = Bs[(kb + 4) * 136 + n];
            }
#pragma unroll
            for (int mi = 0; mi < 4; mi++)
#pragma unroll
                for (int ni = 0; ni < 4; ni++)
                    mma8(acc[mi][ni], a[mi], b[ni]);
        }
        if (kt < 63) {
            __syncthreads();
            deposit();
            __syncthreads();
        }
    }

#pragma unroll
    for (int mi = 0; mi < 4; mi++) {
        int r = m0 + mw + mi * 16 + (lane >> 2);
#pragma unroll
        for (int ni = 0; ni < 4; ni++) {
            int cn = n0 + nw + ni * 8 + (lane & 3) * 2;
            float bx = bias[cn], by = bias[cn + 1];
            float2 lo = { acc[mi][ni][0] + bx, acc[mi][ni][1] + by };
            float2 hi = { acc[mi][ni][2] + bx, acc[mi][ni][3] + by };
            if (C_SCATTER) {
                int h = cn >> 6, d = cn & 63;
                int b0 = r >> 11, s2 = r & 2047;
                *(float2*)&C[(((size_t)(b0 * NHEAD + h)) * S_LEN + s2) * DK + d] = lo;
                int r2 = r + 8, b1 = r2 >> 11, s3 = r2 & 2047;
                *(float2*)&C[(((size_t)(b1 * NHEAD + h)) * S_LEN + s3) * DK + d] = hi;
            } else {
                *(float2*)&C[(size_t)r * D_MODEL + cn] = lo;
                *(float2*)&C[(size_t)(r + 8) * D_MODEL + cn] = hi;
            }
        }
    }
}

__global__ void __launch_bounds__(256) proj_kernel(
    const float* __restrict__ Xq, const float* __restrict__ Xk, const float* __restrict__ Xv,
    const float* __restrict__ Wq, const float* __restrict__ Wk, const float* __restrict__ Wv,
    const float* __restrict__ bq, const float* __restrict__ bk, const float* __restrict__ bv)
{
    int z = blockIdx.z;
    const float* A    = (z == 0) ? Xq : (z == 1) ? Xk : Xv;
    const float* W    = (z == 0) ? Wq : (z == 1) ? Wk : Wv;
    const float* bias = (z == 0) ? bq : (z == 1) ? bk : bv;
    float*       Cp   = (z == 0) ? g_q : (z == 1) ? g_k : g_v;
    mma_gemm<0, 1>(A, W, bias, Cp);
}

__global__ void __launch_bounds__(256) outproj_kernel(
    const float* __restrict__ Wo, const float* __restrict__ bo, float* __restrict__ C)
{
    mma_gemm<1, 0>(g_o, Wo, bo, C);
}

// =========================================================================
// Flash attention with relative positional bias; GEMMs on mma.sync tf32.
// One block = 64 query rows of one (b,h), 256 threads.
// SMEM (floats):
//   Qs [64][68]  row-major            @ 0       (4352)
//   KP [192][68] row-major (j rows)   @ 4352    (13056)   [SC 64x196 ALIASES]
//   Ps [64][68]  row-major            @ 17408   (4352)
//   Vs [64][72]  row-major            @ 21760   (4608)
//   AL[64] @ 26368, LS[64] @ 26432 -> 26496 floats = 105984 B
// =========================================================================
#define QS_OFF 0
#define KP_OFF 4352
#define SC_OFF 4352
#define PS_OFF 17408
#define VS_OFF 21760
#define AL_OFF 26368
#define LS_OFF 26432
#define FLASH_SMEM_BYTES (26496 * 4)

__global__ void __launch_bounds__(256, 2) flash_kernel(const float* __restrict__ pe)
{
    extern __shared__ float sm[];
    uint32_t* smu = (uint32_t*)sm;
    const int tid  = threadIdx.x;
    const int lane = tid & 31;
    const int wid  = tid >> 5;
    const int bh  = blockIdx.y;
    const int rt  = (int)gridDim.x - 1 - (int)blockIdx.x;  // heavy tiles first
    const int r0  = rt * 64;

    const float* Qg = g_q + (size_t)bh * S_LEN * DK;
    const float* Kg = g_k + (size_t)bh * S_LEN * DK;
    const float* Vg = g_v + (size_t)bh * S_LEN * DK;
    float*       Og = g_o + (size_t)bh * S_LEN * DK;

    // score-phase warp mapping: warp covers 24 score columns
    const int nsc = wid * 24;
    // PV-phase warp mapping: 4x2 grid, warp tile 16m x 32n
    const int mw2 = (wid & 3) * 16;
    const int nw2 = (wid >> 2) * 32;

    // ---- load Q tile (tf32-converted, stride 68) ----
#pragma unroll
    for (int i = 0; i < 4; i++) {
        int idx = tid + i * 256;
        int r = idx >> 4, dq = (idx & 15) << 2;
        float4 v = *(const float4*)&Qg[(size_t)(r0 + r) * DK + dq];
        smu[QS_OFF + r * 68 + dq + 0] = f2tf32(v.x);
        smu[QS_OFF + r * 68 + dq + 1] = f2tf32(v.y);
        smu[QS_OFF + r * 68 + dq + 2] = f2tf32(v.z);
        smu[QS_OFF + r * 68 + dq + 3] = f2tf32(v.w);
    }

    float Oacc[4][4];
#pragma unroll
    for (int i = 0; i < 4; i++)
#pragma unroll
        for (int j = 0; j < 4; j++) Oacc[i][j] = 0.f;
    float m_old = -1.0e30f;
    float l_old = 0.f;

    const int ntiles = rt + 1;
    for (int t = 0; t < ntiles; t++) {
        const int c0 = t * 64;
        const int base_lo = S_LEN - 64 - r0 + c0;   // PE band: l = base_lo + jr
        __syncthreads();   // previous PV done before overwriting KP/Vs

        // ---- K tile -> KP rows 0..63 ----
#pragma unroll
        for (int i = 0; i < 4; i++) {
            int idx = tid + i * 256;
            int r = idx >> 4, dq = (idx & 15) << 2;
            float4 v = *(const float4*)&Kg[(size_t)(c0 + r) * DK + dq];
            smu[KP_OFF + r * 68 + dq + 0] = f2tf32(v.x);
            smu[KP_OFF + r * 68 + dq + 1] = f2tf32(v.y);
            smu[KP_OFF + r * 68 + dq + 2] = f2tf32(v.z);
            smu[KP_OFF + r * 68 + dq + 3] = f2tf32(v.w);
        }
        // ---- PE band -> KP rows 64..190, row 191 zero ----
#pragma unroll
        for (int i = 0; i < 8; i++) {
            int idx = tid + i * 256;          // 0..2047
            int jr = idx >> 4, dq = (idx & 15) << 2;
            float4 v = make_float4(0.f, 0.f, 0.f, 0.f);
            if (jr < 127) {
                int l = base_lo + jr;
                if (l >= 0 && l < S_LEN) v = *(const float4*)&pe[(size_t)l * DK + dq];
            }
            int row = 64 + jr;
            smu[KP_OFF + row * 68 + dq + 0] = f2tf32(v.x);
            smu[KP_OFF + row * 68 + dq + 1] = f2tf32(v.y);
            smu[KP_OFF + row * 68 + dq + 2] = f2tf32(v.z);
            smu[KP_OFF + row * 68 + dq + 3] = f2tf32(v.w);
        }
        // ---- V tile -> Vs (stride 72) ----
#pragma unroll
        for (int i = 0; i < 4; i++) {
            int idx = tid + i * 256;
            int c = idx >> 4, dq = (idx & 15) << 2;
            float4 v = *(const float4*)&Vg[(size_t)(c0 + c) * DK + dq];
            smu[VS_OFF + c * 72 + dq + 0] = f2tf32(v.x);
            smu[VS_OFF + c * 72 + dq + 1] = f2tf32(v.y);
            smu[VS_OFF + c * 72 + dq + 2] = f2tf32(v.z);
            smu[VS_OFF + c * 72 + dq + 3] = f2tf32(v.w);
        }
        __syncthreads();

        // ---- score mma: SC[64,192] = Q @ KP^T; warp covers cols nsc..nsc+23 ----
        float sc[4][3][4];
#pragma unroll
        for (int mi = 0; mi < 4; mi++)
#pragma unroll
            for (int ni = 0; ni < 3; ni++)
#pragma unroll
                for (int q = 0; q < 4; q++) sc[mi][ni][q] = 0.f;

#pragma unroll
        for (int d8 = 0; d8 < 8; d8++) {
            const int kb = d8 * 8 + (lane & 3);
            uint32_t a[4][4], b[3][2];
#pragma unroll
            for (int mi = 0; mi < 4; mi++) {
                int r = mi * 16 + (lane >> 2);
                a[mi][0] = smu[QS_OFF + r * 68 + kb];
                a[mi][1] = smu[QS_OFF + (r + 8) * 68 + kb];
                a[mi][2] = smu[QS_OFF + r * 68 + kb + 4];
                a[mi][3] = smu[QS_OFF + (r + 8) * 68 + kb + 4];
            }
#pragma unroll
            for (int ni = 0; ni < 3; ni++) {
                int n = nsc + ni * 8 + (lane >> 2);
                b[ni][0] = smu[KP_OFF + n * 68 + kb];
                b[ni][1] = smu[KP_OFF + n * 68 + kb + 4];
            }
#pragma unroll
            for (int mi = 0; mi < 4; mi++)
#pragma unroll
                for (int ni = 0; ni < 3; ni++)
                    mma8(sc[mi][ni], a[mi], b[ni]);
        }
        __syncthreads();   // everyone done reading KP before SC (alias) overwrite

        // ---- dump score frags -> SC (row-major stride 196) ----
#pragma unroll
        for (int mi = 0; mi < 4; mi++) {
            int row = mi * 16 + (lane >> 2);
#pragma unroll
            for (int ni = 0; ni < 3; ni++) {
                int col = nsc + ni * 8 + (lane & 3) * 2;
                *(float2*)&sm[SC_OFF + row * 196 + col] =
                    make_float2(sc[mi][ni][0], sc[mi][ni][1]);
                *(float2*)&sm[SC_OFF + (row + 8) * 196 + col] =
                    make_float2(sc[mi][ni][2], sc[mi][ni][3]);
            }
        }
        __syncthreads();

        // ---- softmax (4 threads per row, 16 cols each) ----
        {
            const int r  = tid >> 2;
            const int gr = r0 + r;
            const int cb = (tid & 3) * 16;
            float s[16];
            float mt = -1.0e30f;
#pragma unroll
            for (int i = 0; i < 16; i++) {
                int c = cb + i;
                float val = (sm[SC_OFF + r * 196 + c] +
                             sm[SC_OFF + r * 196 + 127 + c - r]) * 0.125f;
                if (c0 + c > gr) val = -1.0e9f;   // exact ref mask value
                s[i] = val;
                mt = fmaxf(mt, val);
            }
            mt = fmaxf(mt, __shfl_xor_sync(0xffffffffu, mt, 1));
            mt = fmaxf(mt, __shfl_xor_sync(0xffffffffu, mt, 2));
            float m_new = fmaxf(m_old, mt);
            float al = __expf(m_old - m_new);
            float psum = 0.f;
            uint32_t pq[16];
#pragma unroll
            for (int i = 0; i < 16; i++) {
                float p = __expf(s[i] - m_new);
                psum += p;
                pq[i] = f2tf32(p);
            }
#pragma unroll
            for (int q = 0; q < 4; q++) {
                uint4 pk = make_uint4(pq[q * 4], pq[q * 4 + 1], pq[q * 4 + 2], pq[q * 4 + 3]);
                *(uint4*)&smu[PS_OFF + r * 68 + cb + q * 4] = pk;
            }
            psum += __shfl_xor_sync(0xffffffffu, psum, 1);
            psum += __shfl_xor_sync(0xffffffffu, psum, 2);
            float l_new = fmaf(al, l_old, psum);
            m_old = m_new;
            l_old = l_new;
            if ((tid & 3) == 0) {
                sm[AL_OFF + r] = al;
                sm[LS_OFF + r] = l_new;
            }
        }
        __syncthreads();

        // ---- PV mma: O += P @ V; warp tile 16m x 32n ----
        {
            float al0 = sm[AL_OFF + mw2 + (lane >> 2)];
            float al1 = sm[AL_OFF + mw2 + (lane >> 2) + 8];
#pragma unroll
            for (int ni = 0; ni < 4; ni++) {
                Oacc[ni][0] *= al0; Oacc[ni][1] *= al0;
                Oacc[ni][2] *= al1; Oacc[ni][3] *= al1;
            }
#pragma unroll
            for (int c8 = 0; c8 < 8; c8++) {
                const int kb = c8 * 8 + (lane & 3);
                uint32_t a[4], b[4][2];
                int rr = mw2 + (lane >> 2);
                a[0] = smu[PS_OFF + rr * 68 + kb];
                a[1] = smu[PS_OFF + (rr + 8) * 68 + kb];
                a[2] = smu[PS_OFF + rr * 68 + kb + 4];
                a[3] = smu[PS_OFF + (rr + 8) * 68 + kb + 4];
#pragma unroll
                for (int ni = 0; ni < 4; ni++) {
                    int n = nw2 + ni * 8 + (lane >> 2);
                    b[ni][0] = smu[VS_OFF + kb * 72 + n];
                    b[ni][1] = smu[VS_OFF + (kb + 4) * 72 + n];
                }
#pragma unroll
                for (int ni = 0; ni < 4; ni++)
                    mma8(Oacc[ni], a, b[ni]);
            }
        }
    }

    // ---- normalize + store ----
    {
        float inv0 = 1.0f / sm[LS_OFF + mw2 + (lane >> 2)];
        float inv1 = 1.0f / sm[LS_OFF + mw2 + (lane >> 2) + 8];
        int row = r0 + mw2 + (lane >> 2);
#pragma unroll
        for (int ni = 0; ni < 4; ni++) {
            int col = nw2 + ni * 8 + (lane & 3) * 2;
            *(float2*)&Og[(size_t)row * DK + col] =
                make_float2(Oacc[ni][0] * inv0, Oacc[ni][1] * inv0);
            *(float2*)&Og[(size_t)(row + 8) * DK + col] =
                make_float2(Oacc[ni][2] * inv1, Oacc[ni][3] * inv1);
        }
    }
}

// =========================================================================
extern "C" void kernel_launch(void* const* d_in, const int* in_sizes, int n_in,
                              void* d_out, int out_size)
{
    const float* query  = (const float*)d_in[0];
    const float* key    = (const float*)d_in[1];
    const float* value  = (const float*)d_in[2];
    const float* key_pe = (const float*)d_in[3];
    const float* Wq = (const float*)d_in[4];
    const float* bq = (const float*)d_in[5];
    const float* Wk = (const float*)d_in[6];
    const float* bk = (const float*)d_in[7];
    const float* Wv = (const float*)d_in[8];
    const float* bv = (const float*)d_in[9];
    const float* Wo = (const float*)d_in[10];
    const float* bo = (const float*)d_in[11];
    float* out = (float*)d_out;

    cudaFuncSetAttribute(flash_kernel,
                         cudaFuncAttributeMaxDynamicSharedMemorySize,
                         FLASH_SMEM_BYTES);

    // 1) Q/K/V projections (mma.sync tf32)
    proj_kernel<<<dim3(8, 32, 3), 256>>>(query, key, value, Wq, Wk, Wv, bq, bk, bv);

    // 2) causal attention + relative positional bias (mma.sync tf32)
    flash_kernel<<<dim3(S_LEN / 64, BHEADS), 256, FLASH_SMEM_BYTES>>>(key_pe);

    // 3) output projection (mma.sync tf32)
    outproj_kernel<<<dim3(8, 32), 256>>>(Wo, bo, out);
}

// round 9
// speedup vs baseline: 2.8579x; 1.0324x over previous
#include <cuda_runtime.h>
#include <cstdint>

#define S_LEN 2048
#define D_MODEL 1024
#define NHEAD 16
#define BATCH 2
#define BHEADS (BATCH * NHEAD)   // 32
#define DK 64
#define MROWS (BATCH * S_LEN)    // 4096
#define PE_ROWS (S_LEN + 128)    // zero-padded PE

// ---------------- scratch (allocation-free: __device__ globals) ----------------
__device__ float g_q[(size_t)BHEADS * S_LEN * DK];
__device__ float g_k[(size_t)BHEADS * S_LEN * DK];
__device__ float g_v[(size_t)BHEADS * S_LEN * DK];
__device__ float g_o[(size_t)BHEADS * S_LEN * DK];
__device__ float g_xc[3ull * MROWS * D_MODEL];       // tf32-rounded inputs
__device__ float g_wc[4ull * D_MODEL * D_MODEL];     // tf32-rounded weights
__device__ float g_pe[(size_t)PE_ROWS * DK];         // tf32-rounded + zero-padded

// ======================= helpers =======================
__device__ __forceinline__ uint32_t f2tf32(float f) {
    uint32_t r;
    asm("cvt.rna.tf32.f32 %0, %1;" : "=r"(r) : "f"(f));
    return r;
}
__device__ __forceinline__ float rnd(float f) { return __uint_as_float(f2tf32(f)); }

#define CPA16(dst, src) \
    asm volatile("cp.async.cg.shared.global [%0], [%1], 16;" \
        :: "r"((uint32_t)__cvta_generic_to_shared(dst)), \
           "l"(__cvta_generic_to_global(src)) : "memory")
#define CPA_COMMIT() asm volatile("cp.async.commit_group;" ::: "memory")
#define CPA_WAIT(n)  asm volatile("cp.async.wait_group %0;" :: "n"(n) : "memory")

// m16n8k8 tf32 mma: A row-major (4 regs), B col-major (2 regs), C f32 (4 regs)
__device__ __forceinline__ void mma8(float c[4], const uint32_t a[4], const uint32_t b[2]) {
    asm volatile(
        "mma.sync.aligned.m16n8k8.row.col.f32.tf32.tf32.f32 "
        "{%0,%1,%2,%3}, {%4,%5,%6,%7}, {%8,%9}, {%0,%1,%2,%3};"
        : "+f"(c[0]), "+f"(c[1]), "+f"(c[2]), "+f"(c[3])
        : "r"(a[0]), "r"(a[1]), "r"(a[2]), "r"(a[3]), "r"(b[0]), "r"(b[1]));
}

// =========================================================================
// prep: tf32-round X / W / pe (pe padded with zeros to PE_ROWS).
// =========================================================================
__global__ void __launch_bounds__(256) prep_kernel(
    const float* __restrict__ q, const float* __restrict__ k, const float* __restrict__ v,
    const float* __restrict__ Wq, const float* __restrict__ Wk,
    const float* __restrict__ Wv, const float* __restrict__ Wo,
    const float* __restrict__ pe)
{
    const int z = blockIdx.z;
    const size_t idx4 = ((size_t)blockIdx.x * 256 + threadIdx.x) * 4;
    if (z == 7) {
        if (idx4 >= (size_t)PE_ROWS * DK) return;
        float4 o;
        if (idx4 < (size_t)S_LEN * DK) {
            float4 x = *(const float4*)&pe[idx4];
            o.x = rnd(x.x); o.y = rnd(x.y); o.z = rnd(x.z); o.w = rnd(x.w);
        } else {
            o = make_float4(0.f, 0.f, 0.f, 0.f);
        }
        *(float4*)&g_pe[idx4] = o;
        return;
    }
    const float* src; float* dst; size_t n;
    if (z < 3) {
        src = (z == 0) ? q : (z == 1) ? k : v;
        dst = g_xc + (size_t)z * MROWS * D_MODEL;
        n = (size_t)MROWS * D_MODEL;
    } else {
        int w = z - 3;
        src = (w == 0) ? Wq : (w == 1) ? Wk : (w == 2) ? Wv : Wo;
        dst = g_wc + (size_t)w * D_MODEL * D_MODEL;
        n = (size_t)D_MODEL * D_MODEL;
    }
    if (idx4 >= n) return;
    float4 x = *(const float4*)&src[idx4];
    float4 o;
    o.x = rnd(x.x); o.y = rnd(x.y); o.z = rnd(x.z); o.w = rnd(x.w);
    *(float4*)&dst[idx4] = o;
}

// =========================================================================
// Dense GEMM via mma.sync tf32, cp.async double-buffered, 1 sync per k-tile.
// C[4096,1024] = A[4096,1024] @ W[1024,1024] + bias.   Inputs pre-rounded.
// Block 128x128, 8 warps (2m x 4n), warp tile 64x32, BK=16.
// =========================================================================
template<int A_GATHER, int C_SCATTER>
__device__ __forceinline__ void mma_gemm(
    const float* __restrict__ A, const float* __restrict__ W,
    const float* __restrict__ bias, float* __restrict__ C)
{
    __shared__ float As[2][128 * 20];
    __shared__ float Bs[2][16 * 136];

    const int tid  = threadIdx.x;
    const int lane = tid & 31;
    const int wid  = tid >> 5;
    const int mw = (wid >> 2) * 64;
    const int nw = (wid & 3) * 32;
    const int m0 = blockIdx.y * 128;
    const int n0 = blockIdx.x * 128;

    auto stage = [&](int k0, int buf) {
#pragma unroll
        for (int i = 0; i < 2; i++) {
            int idx = tid + i * 256;
            int m = idx >> 2, kq = (idx & 3) << 2;
            const float* srcA;
            if (A_GATHER) {
                int gm = m0 + m, b = gm >> 11, s2 = gm & 2047;
                int gk = k0 + kq, h = gk >> 6, d = gk & 63;
                srcA = &A[(((size_t)(b * NHEAD + h)) * S_LEN + s2) * DK + d];
            } else {
                srcA = &A[(size_t)(m0 + m) * D_MODEL + k0 + kq];
            }
            CPA16(&As[buf][m * 20 + kq], srcA);
            int kk = idx >> 5, nq = (idx & 31) << 2;
            CPA16(&Bs[buf][kk * 136 + nq], &W[(size_t)(k0 + kk) * D_MODEL + n0 + nq]);
        }
    };

    float acc[4][4][4];
#pragma unroll
    for (int mi = 0; mi < 4; mi++)
#pragma unroll
        for (int ni = 0; ni < 4; ni++)
#pragma unroll
            for (int q = 0; q < 4; q++) acc[mi][ni][q] = 0.f;

    stage(0, 0);
    CPA_COMMIT();
    CPA_WAIT(0);
    __syncthreads();

    for (int kt = 0; kt < 64; kt++) {
        const int buf = kt & 1;
        if (kt < 63) { stage((kt + 1) * 16, buf ^ 1); CPA_COMMIT(); }
        const uint32_t* Au = reinterpret_cast<const uint32_t*>(As[buf]);
        const uint32_t* Bu = reinterpret_cast<const uint32_t*>(Bs[buf]);
#pragma unroll
        for (int k8 = 0; k8 < 2; k8++) {
            const int kb = k8 * 8 + (lane & 3);
            uint32_t a[4][4], b[4][2];
#pragma unroll
            for (int mi = 0; mi < 4; mi++) {
                int r = mw + mi * 16 + (lane >> 2);
                a[mi][0] = Au[r * 20 + kb];
                a[mi][1] = Au[(r + 8) * 20 + kb];
                a[mi][2] = Au[r * 20 + kb + 4];
                a[mi][3] = Au[(r + 8) * 20 + kb + 4];
            }
#pragma unroll
            for (int ni = 0; ni < 4; ni++) {
                int n = nw + ni * 8 + (lane >> 2);
                b[ni][0] = Bu[kb * 136 + n];
                b[ni][1] = Bu[(kb + 4) * 136 + n];
            }
#pragma unroll
            for (int mi = 0; mi < 4; mi++)
#pragma unroll
                for (int ni = 0; ni < 4; ni++)
                    mma8(acc[mi][ni], a[mi], b[ni]);
        }
        if (kt < 63) {
            CPA_WAIT(0);
            __syncthreads();
        }
    }

    // epilogue: + bias; C_SCATTER path stores tf32-pre-rounded for downstream
#pragma unroll
    for (int mi = 0; mi < 4; mi++) {
        int r = m0 + mw + mi * 16 + (lane >> 2);
#pragma unroll
        for (int ni = 0; ni < 4; ni++) {
            int cn = n0 + nw + ni * 8 + (lane & 3) * 2;
            float bx = bias[cn], by = bias[cn + 1];
            float2 lo, hi;
            if (C_SCATTER) {
                lo = make_float2(rnd(acc[mi][ni][0] + bx), rnd(acc[mi][ni][1] + by));
                hi = make_float2(rnd(acc[mi][ni][2] + bx), rnd(acc[mi][ni][3] + by));
                int h = cn >> 6, d = cn & 63;
                int b0 = r >> 11, s2 = r & 2047;
                *(float2*)&C[(((size_t)(b0 * NHEAD + h)) * S_LEN + s2) * DK + d] = lo;
                int r2 = r + 8, b1 = r2 >> 11, s3 = r2 & 2047;
                *(float2*)&C[(((size_t)(b1 * NHEAD + h)) * S_LEN + s3) * DK + d] = hi;
            } else {
                lo = make_float2(acc[mi][ni][0] + bx, acc[mi][ni][1] + by);
                hi = make_float2(acc[mi][ni][2] + bx, acc[mi][ni][3] + by);
                *(float2*)&C[(size_t)r * D_MODEL + cn] = lo;
                *(float2*)&C[(size_t)(r + 8) * D_MODEL + cn] = hi;
            }
        }
    }
}

__global__ void __launch_bounds__(256) proj_kernel(
    const float* __restrict__ bq, const float* __restrict__ bk, const float* __restrict__ bv)
{
    int z = blockIdx.z;
    const float* A    = g_xc + (size_t)z * MROWS * D_MODEL;
    const float* W    = g_wc + (size_t)z * D_MODEL * D_MODEL;
    const float* bias = (z == 0) ? bq : (z == 1) ? bk : bv;
    float*       Cp   = (z == 0) ? g_q : (z == 1) ? g_k : g_v;
    mma_gemm<0, 1>(A, W, bias, Cp);
}

__global__ void __launch_bounds__(256) outproj_kernel(
    const float* __restrict__ bo, float* __restrict__ C)
{
    mma_gemm<1, 0>(g_o, g_wc + 3ull * D_MODEL * D_MODEL, bo, C);
}

// =========================================================================
// Flash attention; cp.async staging of pre-rounded Q/K/V/PE; mma.sync tf32.
// One block = 64 query rows of one (b,h), 256 threads.
// SMEM (floats):
//   Qs [64][68]  @ 0       (4352)
//   KP [192][68] @ 4352    (13056)  rows 0-63 K, 64-191 PE  [SC 64x196 ALIASES]
//   Ps [64][68]  @ 17408   (4352)
//   Vs [64][72]  @ 21760   (4608)
//   AL[64] @ 26368, LS[64] @ 26432 -> 26496 floats = 105984 B
// =========================================================================
#define QS_OFF 0
#define KP_OFF 4352
#define SC_OFF 4352
#define PS_OFF 17408
#define VS_OFF 21760
#define AL_OFF 26368
#define LS_OFF 26432
#define FLASH_SMEM_BYTES (26496 * 4)

__global__ void __launch_bounds__(256, 2) flash_kernel()
{
    extern __shared__ float sm[];
    uint32_t* smu = (uint32_t*)sm;
    const int tid  = threadIdx.x;
    const int lane = tid & 31;
    const int wid  = tid >> 5;
    const int bh  = blockIdx.y;
    const int rt  = (int)gridDim.x - 1 - (int)blockIdx.x;  // heavy tiles first
    const int r0  = rt * 64;

    const float* Qg = g_q + (size_t)bh * S_LEN * DK;
    const float* Kg = g_k + (size_t)bh * S_LEN * DK;
    const float* Vg = g_v + (size_t)bh * S_LEN * DK;
    float*       Og = g_o + (size_t)bh * S_LEN * DK;

    const int nsc = wid * 24;          // score phase: 24 cols per warp
    const int mw2 = (wid & 3) * 16;    // PV phase: 4m x 2n warp grid
    const int nw2 = (wid >> 2) * 32;

    // ---- Q tile via cp.async (pre-rounded) ----
#pragma unroll
    for (int i = 0; i < 4; i++) {
        int idx = tid + i * 256;
        int r = idx >> 4, dq = (idx & 15) << 2;
        CPA16(&sm[QS_OFF + r * 68 + dq], &Qg[(size_t)(r0 + r) * DK + dq]);
    }
    CPA_COMMIT();

    float Oacc[4][4];
#pragma unroll
    for (int i = 0; i < 4; i++)
#pragma unroll
        for (int j = 0; j < 4; j++) Oacc[i][j] = 0.f;
    float m_old = -1.0e30f;
    float l_old = 0.f;

    const int ntiles = rt + 1;
    for (int t = 0; t < ntiles; t++) {
        const int c0 = t * 64;
        const int base_lo = S_LEN - 64 - r0 + c0;   // >= 0; max +127 < PE_ROWS
        __syncthreads();   // (1) prior PV/softmax done: KP/Vs/Ps free

        // ---- group A: K rows 0-63 + PE rows 64-191 ----
#pragma unroll
        for (int i = 0; i < 4; i++) {
            int idx = tid + i * 256;
            int r = idx >> 4, dq = (idx & 15) << 2;
            CPA16(&sm[KP_OFF + r * 68 + dq], &Kg[(size_t)(c0 + r) * DK + dq]);
        }
#pragma unroll
        for (int i = 0; i < 8; i++) {
            int idx = tid + i * 256;
            int jr = idx >> 4, dq = (idx & 15) << 2;
            CPA16(&sm[KP_OFF + (64 + jr) * 68 + dq],
                  &g_pe[(size_t)(base_lo + jr) * DK + dq]);
        }
        CPA_COMMIT();
        // ---- group B: V (overlapped with score mma) ----
#pragma unroll
        for (int i = 0; i < 4; i++) {
            int idx = tid + i * 256;
            int c = idx >> 4, dq = (idx & 15) << 2;
            CPA16(&sm[VS_OFF + c * 72 + dq], &Vg[(size_t)(c0 + c) * DK + dq]);
        }
        CPA_COMMIT();
        CPA_WAIT(1);       // Q (first iter) + K/PE complete; V may be in flight
        __syncthreads();   // (2) staged data visible

        // ---- score mma: SC[64,192] = Q @ KP^T ----
        float sc[4][3][4];
#pragma unroll
        for (int mi = 0; mi < 4; mi++)
#pragma unroll
            for (int ni = 0; ni < 3; ni++)
#pragma unroll
                for (int q = 0; q < 4; q++) sc[mi][ni][q] = 0.f;

#pragma unroll
        for (int d8 = 0; d8 < 8; d8++) {
            const int kb = d8 * 8 + (lane & 3);
            uint32_t a[4][4], b[3][2];
#pragma unroll
            for (int mi = 0; mi < 4; mi++) {
                int r = mi * 16 + (lane >> 2);
                a[mi][0] = smu[QS_OFF + r * 68 + kb];
                a[mi][1] = smu[QS_OFF + (r + 8) * 68 + kb];
                a[mi][2] = smu[QS_OFF + r * 68 + kb + 4];
                a[mi][3] = smu[QS_OFF + (r + 8) * 68 + kb + 4];
            }
#pragma unroll
            for (int ni = 0; ni < 3; ni++) {
                int n = nsc + ni * 8 + (lane >> 2);
                b[ni][0] = smu[KP_OFF + n * 68 + kb];
                b[ni][1] = smu[KP_OFF + n * 68 + kb + 4];
            }
#pragma unroll
            for (int mi = 0; mi < 4; mi++)
#pragma unroll
                for (int ni = 0; ni < 3; ni++)
                    mma8(sc[mi][ni], a[mi], b[ni]);
        }
        __syncthreads();   // (3) KP reads done before SC (alias) overwrite

        // ---- dump score frags -> SC (row-major stride 196) ----
#pragma unroll
        for (int mi = 0; mi < 4; mi++) {
            int row = mi * 16 + (lane >> 2);
#pragma unroll
            for (int ni = 0; ni < 3; ni++) {
                int col = nsc + ni * 8 + (lane & 3) * 2;
                *(float2*)&sm[SC_OFF + row * 196 + col] =
                    make_float2(sc[mi][ni][0], sc[mi][ni][1]);
                *(float2*)&sm[SC_OFF + (row + 8) * 196 + col] =
                    make_float2(sc[mi][ni][2], sc[mi][ni][3]);
            }
        }
        __syncthreads();   // (4)

        // ---- softmax (4 threads per row, 16 cols each) ----
        {
            const int r  = tid >> 2;
            const int gr = r0 + r;
            const int cb = (tid & 3) * 16;
            float s[16];
            float mt = -1.0e30f;
#pragma unroll
            for (int i = 0; i < 16; i++) {
                int c = cb + i;
                float val = (sm[SC_OFF + r * 196 + c] +
                             sm[SC_OFF + r * 196 + 127 + c - r]) * 0.125f;
                if (c0 + c > gr) val = -1.0e9f;   // exact ref mask value
                s[i] = val;
                mt = fmaxf(mt, val);
            }
            mt = fmaxf(mt, __shfl_xor_sync(0xffffffffu, mt, 1));
            mt = fmaxf(mt, __shfl_xor_sync(0xffffffffu, mt, 2));
            float m_new = fmaxf(m_old, mt);
            float al = __expf(m_old - m_new);
            float psum = 0.f;
            uint32_t pq[16];
#pragma unroll
            for (int i = 0; i < 16; i++) {
                float p = __expf(s[i] - m_new);
                psum += p;
                pq[i] = f2tf32(p);
            }
#pragma unroll
            for (int q = 0; q < 4; q++) {
                uint4 pk = make_uint4(pq[q * 4], pq[q * 4 + 1], pq[q * 4 + 2], pq[q * 4 + 3]);
                *(uint4*)&smu[PS_OFF + r * 68 + cb + q * 4] = pk;
            }
            psum += __shfl_xor_sync(0xffffffffu, psum, 1);
            psum += __shfl_xor_sync(0xffffffffu, psum, 2);
            float l_new = fmaf(al, l_old, psum);
            m_old = m_new;
            l_old = l_new;
            if ((tid & 3) == 0) {
                sm[AL_OFF + r] = al;
                sm[LS_OFF + r] = l_new;
            }
        }
        CPA_WAIT(0);       // V landed
        __syncthreads();   // (5) Ps/AL/Vs visible

        // ---- PV mma: O += P @ V; warp tile 16m x 32n ----
        {
            float al0 = sm[AL_OFF + mw2 + (lane >> 2)];
            float al1 = sm[AL_OFF + mw2 + (lane >> 2) + 8];
#pragma unroll
            for (int ni = 0; ni < 4; ni++) {
                Oacc[ni][0] *= al0; Oacc[ni][1] *= al0;
                Oacc[ni][2] *= al1; Oacc[ni][3] *= al1;
            }
#pragma unroll
            for (int c8 = 0; c8 < 8; c8++) {
                const int kb = c8 * 8 + (lane & 3);
                uint32_t a[4], b[4][2];
                int rr = mw2 + (lane >> 2);
                a[0] = smu[PS_OFF + rr * 68 + kb];
                a[1] = smu[PS_OFF + (rr + 8) * 68 + kb];
                a[2] = smu[PS_OFF + rr * 68 + kb + 4];
                a[3] = smu[PS_OFF + (rr + 8) * 68 + kb + 4];
#pragma unroll
                for (int ni = 0; ni < 4; ni++) {
                    int n = nw2 + ni * 8 + (lane >> 2);
                    b[ni][0] = smu[VS_OFF + kb * 72 + n];
                    b[ni][1] = smu[VS_OFF + (kb + 4) * 72 + n];
                }
#pragma unroll
                for (int ni = 0; ni < 4; ni++)
                    mma8(Oacc[ni], a, b[ni]);
            }
        }
    }

    // ---- normalize + store (tf32-pre-rounded for outproj cp.async) ----
    {
        float inv0 = 1.0f / sm[LS_OFF + mw2 + (lane >> 2)];
        float inv1 = 1.0f / sm[LS_OFF + mw2 + (lane >> 2) + 8];
        int row = r0 + mw2 + (lane >> 2);
#pragma unroll
        for (int ni = 0; ni < 4; ni++) {
            int col = nw2 + ni * 8 + (lane & 3) * 2;
            *(float2*)&Og[(size_t)row * DK + col] =
                make_float2(rnd(Oacc[ni][0] * inv0), rnd(Oacc[ni][1] * inv0));
            *(float2*)&Og[(size_t)(row + 8) * DK + col] =
                make_float2(rnd(Oacc[ni][2] * inv1), rnd(Oacc[ni][3] * inv1));
        }
    }
}

// =========================================================================
extern "C" void kernel_launch(void* const* d_in, const int* in_sizes, int n_in,
                              void* d_out, int out_size)
{
    const float* query  = (const float*)d_in[0];
    const float* key    = (const float*)d_in[1];
    const float* value  = (const float*)d_in[2];
    const float* key_pe = (const float*)d_in[3];
    const float* Wq = (const float*)d_in[4];
    const float* bq = (const float*)d_in[5];
    const float* Wk = (const float*)d_in[6];
    const float* bk = (const float*)d_in[7];
    const float* Wv = (const float*)d_in[8];
    const float* bv = (const float*)d_in[9];
    const float* Wo = (const float*)d_in[10];
    const float* bo = (const float*)d_in[11];
    float* out = (float*)d_out;

    cudaFuncSetAttribute(flash_kernel,
                         cudaFuncAttributeMaxDynamicSharedMemorySize,
                         FLASH_SMEM_BYTES);

    // 0) tf32-round inputs/weights/pe (pe zero-padded)
    prep_kernel<<<dim3(4096, 1, 8), 256>>>(query, key, value, Wq, Wk, Wv, Wo, key_pe);

    // 1) Q/K/V projections (cp.async + mma.sync tf32)
    proj_kernel<<<dim3(8, 32, 3), 256>>>(bq, bk, bv);

    // 2) causal attention + relative positional bias (cp.async + mma.sync tf32)
    flash_kernel<<<dim3(S_LEN / 64, BHEADS), 256, FLASH_SMEM_BYTES>>>();

    // 3) output projection
    outproj_kernel<<<dim3(8, 32), 256>>>(bo, out);
}